// round 5
// baseline (speedup 1.0000x reference)
#include <cuda_runtime.h>
#include <cuda_bf16.h>
#include <cstdint>

// Problem constants (fixed-shape benchmark)
#define B 8
#define C 256
#define H 128
#define W 128
#define HW (H * W)
#define CO 21
#define NSEG (B * CO)
#define EPS 1e-12f

#define N_FEAT (B * C * H * W)      // 33554432
#define N_OUT  (B * CO * H * W)     // 2752512
#define N_LAB  (B * H * W)          // 131072

// ---------------- scratch (device globals; no allocation) ----------------
__device__ unsigned char g_seg[B * HW];     // per-pixel class id (0..20)
__device__ float g_cnt[NSEG];               // per-segment pixel count (unique writer)
__device__ float g_sum_cur[NSEG * C];       // segment sums (features)
__device__ float g_sum_ref[NSEG * C];       // segment sums (features_old)
__device__ float g_nsq_cur[NSEG];           // per-row sum of squares (atomic accum)
__device__ float g_nsq_ref[NSEG];
__device__ float g_k;                       // number of valid prototypes
__device__ float g_sq;                      // sum of squared gram diffs (masked)
__device__ unsigned int g_ticket;           // last-block finalize ticket

// ---------------- kernel 1: pseudo labels (4 px/thread) + zero scratch ----------------
// grid: (HW/4/256 = 16, B), block: 256
__global__ void k_pseudo(const float* __restrict__ outputs_old,
                         const int* __restrict__ labels,
                         const int* __restrict__ num_old_ptr) {
    int b = blockIdx.y;
    int g = blockIdx.x * 256 + threadIdx.x;        // float4-group index, 0..4095

    if (blockIdx.x == 0 && b == 0) {
        if (threadIdx.x == 0) { g_sq = 0.0f; g_k = 0.0f; g_ticket = 0u; }
        if (threadIdx.x < NSEG) { g_nsq_cur[threadIdx.x] = 0.0f; g_nsq_ref[threadIdx.x] = 0.0f; }
    }

    int nold = *num_old_ptr;
    const float4* oo = (const float4*)(outputs_old + (size_t)b * CO * HW) + g;

    float4 best = __ldg(oo);
    int bx = 0, by = 0, bz = 0, bw = 0;
#pragma unroll
    for (int c = 1; c < CO; ++c) {
        float4 v = __ldg(oo + (size_t)c * (HW / 4));
        if (v.x > best.x) { best.x = v.x; bx = c; }
        if (v.y > best.y) { best.y = v.y; by = c; }
        if (v.z > best.z) { best.z = v.z; bz = c; }
        if (v.w > best.w) { best.w = v.w; bw = c; }
    }
    int4 lv = __ldg((const int4*)(labels + (size_t)b * HW) + g);
    uchar4 r;
    r.x = (unsigned char)((lv.x < nold) ? bx : 0);
    r.y = (unsigned char)((lv.y < nold) ? by : 0);
    r.z = (unsigned char)((lv.z < nold) ? bz : 0);
    r.w = (unsigned char)((lv.w < nold) ? bw : 0);
    ((uchar4*)(g_seg + (size_t)b * HW))[g] = r;
}

// ---------------- kernel 2: segment sums + counts + norm-squares ----------------
// grid: (C+1, B), block: 256.
//   c <  C : one block owns one (b,c) plane; float2-interleaved conflict-free scatter
//   c == C : histogram block -> g_cnt (unique writer) + g_k
__global__ __launch_bounds__(256) void k_segsum(const float* __restrict__ features,
                                                const float* __restrict__ features_old) {
    __shared__ float2 acc[CO * 256];               // {cur, ref} interleaved, 43008 B
    int tid = threadIdx.x;
    int c = blockIdx.x;
    int b = blockIdx.y;

    const uchar4* __restrict__ sg = (const uchar4*)(g_seg + (size_t)b * HW);

    if (c == C) {
        __shared__ int hist[CO];
        if (tid < CO) hist[tid] = 0;
        __syncthreads();
#pragma unroll 4
        for (int it = 0; it < 16; ++it) {
            uchar4 s4 = sg[it * 256 + tid];
            atomicAdd(&hist[(int)s4.x], 1);
            atomicAdd(&hist[(int)s4.y], 1);
            atomicAdd(&hist[(int)s4.z], 1);
            atomicAdd(&hist[(int)s4.w], 1);
        }
        __syncthreads();
        if (tid < CO) g_cnt[b * CO + tid] = (float)hist[tid];
        if (tid == 0) {
            float kk = 0.0f;
            for (int s = 1; s < CO; ++s) if (hist[s] > 0) kk += 1.0f;
            atomicAdd(&g_k, kk);
        }
        return;
    }

#pragma unroll
    for (int s = 0; s < CO; ++s) acc[s * 256 + tid] = make_float2(0.0f, 0.0f);
    __syncthreads();

    const float4* __restrict__ fc = (const float4*)(features     + ((size_t)b * C + c) * HW);
    const float4* __restrict__ fr = (const float4*)(features_old + ((size_t)b * C + c) * HW);

    // software-pipelined: prefetch next iteration's 3 loads before accumulating
    float4 xc = __ldg(fc + tid);
    float4 xr = __ldg(fr + tid);
    uchar4 s4 = sg[tid];
#pragma unroll
    for (int it = 0; it < 16; ++it) {
        float4 nc, nr; uchar4 ns;
        if (it < 15) {
            int nidx = (it + 1) * 256 + tid;
            nc = __ldg(fc + nidx);
            nr = __ldg(fr + nidx);
            ns = sg[nidx];
        }
        float2 a0 = acc[(int)s4.x * 256 + tid]; a0.x += xc.x; a0.y += xr.x; acc[(int)s4.x * 256 + tid] = a0;
        float2 a1 = acc[(int)s4.y * 256 + tid]; a1.x += xc.y; a1.y += xr.y; acc[(int)s4.y * 256 + tid] = a1;
        float2 a2 = acc[(int)s4.z * 256 + tid]; a2.x += xc.z; a2.y += xr.z; acc[(int)s4.z * 256 + tid] = a2;
        float2 a3 = acc[(int)s4.w * 256 + tid]; a3.x += xc.w; a3.y += xr.w; acc[(int)s4.w * 256 + tid] = a3;
        xc = nc; xr = nr; s4 = ns;
    }
    __syncthreads();

    int w = tid >> 5, l = tid & 31;
    for (int s = w; s < CO; s += 8) {
        float vc = 0.0f, vr = 0.0f;
#pragma unroll
        for (int q = l; q < 256; q += 32) {
            float2 v = acc[s * 256 + q];
            vc += v.x; vr += v.y;
        }
#pragma unroll
        for (int o = 16; o; o >>= 1) {
            vc += __shfl_down_sync(0xFFFFFFFFu, vc, o);
            vr += __shfl_down_sync(0xFFFFFFFFu, vr, o);
        }
        if (l == 0) {
            int row = b * CO + s;
            g_sum_cur[row * C + c] = vc;
            g_sum_ref[row * C + c] = vr;
            atomicAdd(&g_nsq_cur[row], vc * vc);
            atomicAdd(&g_nsq_ref[row], vr * vr);
        }
    }
}

// ---------------- kernel 3: Gram-difference MSE + finalize ----------------
// grid: NSEG, block: 256. inv-norms precomputed (g_nsq); row-i norm folded
// into the cached row. Invalid rows get rn=0 -> contribute exactly 0.
__global__ void k_loss(float* __restrict__ out) {
    int i = blockIdx.x;
    int tid = threadIdx.x;
    int w = tid >> 5, l = tid & 31;
    __shared__ float spc[256], spr[256];
    __shared__ float s_part[8];

    float cnt_i = g_cnt[i];
    bool valid_i = (cnt_i > 0.0f) && ((i % CO) != 0);
    float part = 0.0f;

    if (valid_i) {
        float den_i = fmaxf(cnt_i, 1.0f);
        float rnc_i = 1.0f / fmaxf(sqrtf(g_nsq_cur[i]), EPS * den_i);
        float rnr_i = 1.0f / fmaxf(sqrtf(g_nsq_ref[i]), EPS * den_i);
        spc[tid] = g_sum_cur[i * C + tid] * rnc_i;
        spr[tid] = g_sum_ref[i * C + tid] * rnr_i;
        __syncthreads();

        float ac[8], ar[8];
#pragma unroll
        for (int q = 0; q < 8; ++q) {
            ac[q] = spc[l + 32 * q];
            ar[q] = spr[l + 32 * q];
        }

        for (int j = w; j < NSEG; j += 8) {
            float cnt_j = g_cnt[j];
            bool valid_j = (cnt_j > 0.0f) && ((j % CO) != 0);
            float den_j = fmaxf(cnt_j, 1.0f);
            float rnc_j = valid_j ? 1.0f / fmaxf(sqrtf(g_nsq_cur[j]), EPS * den_j) : 0.0f;
            float rnr_j = valid_j ? 1.0f / fmaxf(sqrtf(g_nsq_ref[j]), EPS * den_j) : 0.0f;
            const float* qc = g_sum_cur + j * C;
            const float* qr = g_sum_ref + j * C;
            float dc = 0.0f, dr = 0.0f;
#pragma unroll
            for (int q = 0; q < 8; ++q) {
                dc += ac[q] * __ldg(qc + l + 32 * q);
                dr += ar[q] * __ldg(qr + l + 32 * q);
            }
#pragma unroll
            for (int o = 16; o; o >>= 1) {
                dc += __shfl_down_sync(0xFFFFFFFFu, dc, o);
                dr += __shfl_down_sync(0xFFFFFFFFu, dr, o);
            }
            if (l == 0) {
                float d = dc * rnc_j - dr * rnr_j;
                part += d * d;
            }
        }
    } else {
        __syncthreads();   // keep barrier shape uniform (valid_i is block-uniform)
    }

    if (l == 0) s_part[w] = part;
    __syncthreads();
    if (tid == 0) {
        float tot = 0.0f;
#pragma unroll
        for (int q = 0; q < 8; ++q) tot += s_part[q];
        if (tot != 0.0f) atomicAdd(&g_sq, tot);
        __threadfence();
        unsigned int t = atomicAdd(&g_ticket, 1u);
        if (t == NSEG - 1) {
            float k  = g_k;
            float sq = g_sq;
            out[0] = (k > 0.0f) ? (sq / fmaxf(k * k, 1.0f)) : 0.0f;
        }
    }
}

// ---------------- launch ----------------
extern "C" void kernel_launch(void* const* d_in, const int* in_sizes, int n_in,
                              void* d_out, int out_size) {
    // Resolve inputs by element count (robust to metadata ordering).
    const float* features     = nullptr;
    const float* features_old = nullptr;
    const float* outputs_old  = nullptr;
    const int*   labels       = nullptr;
    const int*   num_old      = nullptr;
    for (int i = 0; i < n_in; ++i) {
        int sz = in_sizes[i];
        if (sz == N_FEAT) {
            if (!features) features = (const float*)d_in[i];
            else           features_old = (const float*)d_in[i];
        } else if (sz == N_OUT) {
            outputs_old = (const float*)d_in[i];
        } else if (sz == N_LAB) {
            labels = (const int*)d_in[i];
        } else if (sz == 1) {
            num_old = (const int*)d_in[i];
        }
    }
    float* out = (float*)d_out;

    k_pseudo<<<dim3(HW / 4 / 256, B), 256>>>(outputs_old, labels, num_old);
    k_segsum<<<dim3(C + 1, B), 256>>>(features, features_old);
    k_loss<<<NSEG, 256>>>(out);
}